// round 15
// baseline (speedup 1.0000x reference)
#include <cuda_runtime.h>
#include <cuda_fp16.h>
#include <cstdint>

#define NMAX 100000
#define EMAX 1000000

// ---------------- scratch ----------------
__device__ int    g_deg[NMAX];
__device__ int    g_rowptr[NMAX + 1];
__device__ int    g_cursor[NMAX];
__device__ float  g_invdeg[NMAX];
__device__ int    g_bsums[128];
__device__ int    g_eidx[EMAX];
__device__ __half g_xh[(size_t)NMAX * 64];   // x (fp16)
__device__ __half g_xsh[(size_t)NMAX * 64];  // x @ Ws1 (fp16)
__device__ float  g_xnf[(size_t)NMAX * 64];  // x @ Wn1 (fp32)
__device__ __half g_hh[(size_t)NMAX * 64];   // h (fp16)
__device__ float  g_hnf[(size_t)NMAX * 32];  // h @ Wn2 (fp32)

// ---------------- PTX helpers (all <= sm_80 era, no 'a' gate) ----------------
__device__ __forceinline__ void mma_f16(float c[4], uint32_t a0, uint32_t a1,
                                        uint32_t a2, uint32_t a3,
                                        uint32_t b0, uint32_t b1) {
    asm volatile(
        "mma.sync.aligned.m16n8k16.row.col.f32.f16.f16.f32 "
        "{%0,%1,%2,%3}, {%4,%5,%6,%7}, {%8,%9}, {%0,%1,%2,%3};"
        : "+f"(c[0]), "+f"(c[1]), "+f"(c[2]), "+f"(c[3])
        : "r"(a0), "r"(a1), "r"(a2), "r"(a3), "r"(b0), "r"(b1));
}
__device__ __forceinline__ void ldsm4(uint32_t& r0, uint32_t& r1, uint32_t& r2,
                                      uint32_t& r3, uint32_t addr) {
    asm volatile("ldmatrix.sync.aligned.m8n8.x4.shared.b16 {%0,%1,%2,%3}, [%4];"
        : "=r"(r0), "=r"(r1), "=r"(r2), "=r"(r3) : "r"(addr));
}
__device__ __forceinline__ void cp16(uint32_t saddr, const void* g) {
    asm volatile("cp.async.ca.shared.global [%0], [%1], 16;" :: "r"(saddr), "l"(g));
}
#define CP_COMMIT() asm volatile("cp.async.commit_group;" ::: "memory")

// ---------------- prep: x -> fp16 ----------------
__global__ void k_prep(const float* __restrict__ x, int n) {
    int i = blockIdx.x * blockDim.x + threadIdx.x;
    if (i < n * 32) {
        float2 v = ((const float2*)x)[i];
        ((__half2*)g_xh)[i] = __float22half2_rn(v);
    }
}

// ---------------- CSR build (split kernels, proven fastest) ----------------
__global__ void k_zero_deg(int n) {
    int i = blockIdx.x * blockDim.x + threadIdx.x;
    if (i < n) g_deg[i] = 0;
}

__global__ void k_count(const int* __restrict__ dst, int e) {
    int i = blockIdx.x * blockDim.x + threadIdx.x;
    int i4 = i * 4;
    if (i4 + 3 < e) {
        int4 d = *(const int4*)(dst + i4);
        atomicAdd(&g_deg[d.x], 1);
        atomicAdd(&g_deg[d.y], 1);
        atomicAdd(&g_deg[d.z], 1);
        atomicAdd(&g_deg[d.w], 1);
    } else {
        for (int j = i4; j < e; j++) atomicAdd(&g_deg[dst[j]], 1);
    }
}

__global__ void __launch_bounds__(1024) k_scanA(int n) {
    __shared__ int s[1024];
    int tid = threadIdx.x;
    int i = blockIdx.x * 1024 + tid;
    int v = (i < n) ? g_deg[i] : 0;
    s[tid] = v;
    __syncthreads();
#pragma unroll
    for (int off = 1; off < 1024; off <<= 1) {
        int t = (tid >= off) ? s[tid - off] : 0;
        __syncthreads();
        s[tid] += t;
        __syncthreads();
    }
    if (i < n) g_rowptr[i] = s[tid] - v;
    if (tid == 1023) g_bsums[blockIdx.x] = s[1023];
}

__global__ void __launch_bounds__(1024) k_scanB(int n, int e, int nb) {
    __shared__ int s[128];
    int tid = threadIdx.x;
    if (tid == 0) {
        int run = 0;
        for (int b = 0; b < nb; b++) { int v = g_bsums[b]; s[b] = run; run += v; }
    }
    __syncthreads();
    int boff = s[blockIdx.x];
    int i = blockIdx.x * 1024 + tid;
    if (i < n) {
        int rp = g_rowptr[i] + boff;
        g_rowptr[i] = rp;
        g_cursor[i] = rp;
        int d = g_deg[i];
        g_invdeg[i] = 1.0f / (float)(d > 1 ? d : 1);
    }
    if (i == 0) g_rowptr[n] = e;
}

__global__ void k_scatter(const int* __restrict__ src, const int* __restrict__ dst, int e) {
    int i = blockIdx.x * blockDim.x + threadIdx.x;
    int i4 = i * 4;
    if (i4 + 3 < e) {
        int4 d = *(const int4*)(dst + i4);
        int4 s = *(const int4*)(src + i4);
        g_eidx[atomicAdd(&g_cursor[d.x], 1)] = s.x;
        g_eidx[atomicAdd(&g_cursor[d.y], 1)] = s.y;
        g_eidx[atomicAdd(&g_cursor[d.z], 1)] = s.z;
        g_eidx[atomicAdd(&g_cursor[d.w], 1)] = s.w;
    } else {
        for (int j = i4; j < e; j++)
            g_eidx[atomicAdd(&g_cursor[dst[j]], 1)] = src[j];
    }
}

// ---------------- layer-1 GEMM: [xs|xn] = x @ [Ws1|Wn1], staged epilogue ----------
#define LHP 72
static constexpr int HG1_B = 128 * LHP * 2;                 // 18432 B
static constexpr int HG1_SMEM = HG1_B + 2 * 128 * LHP * 2;  // 55296 B

__global__ void __launch_bounds__(256, 2) k_hgemm1(
    const float* __restrict__ ws, const float* __restrict__ wn, int n, int ntiles)
{
    extern __shared__ char smraw[];
    __half* Bs = (__half*)smraw;                  // [128][LHP]
    __half* As = (__half*)(smraw + HG1_B);        // [2][128][LHP]
    int tid = threadIdx.x, wid = tid >> 5, lane = tid & 31;

    if (blockIdx.x >= (unsigned)ntiles) return;

    for (int idx = tid; idx < 4096; idx += 256) {
        int k = idx >> 6, nn = idx & 63;
        Bs[nn * LHP + k]        = __float2half_rn(ws[idx]);
        Bs[(64 + nn) * LHP + k] = __float2half_rn(wn[idx]);
    }

    {
        int base = blockIdx.x * 128;
        for (int c = tid; c < 1024; c += 256) {
            int r = c >> 3, q = c & 7;
            int node = base + r; if (node >= n) node = n - 1;
            uint32_t sa = (uint32_t)__cvta_generic_to_shared(As + r * LHP + q * 8);
            cp16(sa, g_xh + (size_t)node * 64 + q * 8);
        }
        CP_COMMIT();
    }

    int wm = wid & 3, wq = wid >> 2;
    int g = lane >> 2, t = lane & 3;
    int rowoff = (lane & 7) + ((lane >> 3) & 1) * 8;
    int koff = (lane >> 4) * 8;

    uint32_t As_u32 = (uint32_t)__cvta_generic_to_shared(As);
    uint32_t Bs_u32 = (uint32_t)__cvta_generic_to_shared(Bs);
    uint32_t aoff[2], boff[4];
#pragma unroll
    for (int m = 0; m < 2; m++)
        aoff[m] = (uint32_t)(((wm * 32 + m * 16 + rowoff) * LHP + koff) * 2);
#pragma unroll
    for (int p = 0; p < 4; p++)
        boff[p] = Bs_u32 + (uint32_t)(((wq * 64 + p * 16 + rowoff) * LHP + koff) * 2);

    int buf = 0;
    for (int tile = blockIdx.x; tile < ntiles; tile += gridDim.x, buf ^= 1) {
        int nxt = tile + gridDim.x;
        if (nxt < ntiles) {
            int base = nxt * 128;
            __half* dst = As + (buf ^ 1) * 128 * LHP;
            for (int c = tid; c < 1024; c += 256) {
                int r = c >> 3, q = c & 7;
                int node = base + r; if (node >= n) node = n - 1;
                uint32_t sa = (uint32_t)__cvta_generic_to_shared(dst + r * LHP + q * 8);
                cp16(sa, g_xh + (size_t)node * 64 + q * 8);
            }
            CP_COMMIT();
            asm volatile("cp.async.wait_group 1;" ::: "memory");
        } else {
            asm volatile("cp.async.wait_group 0;" ::: "memory");
        }
        __syncthreads();

        uint32_t Ab = As_u32 + (uint32_t)(buf * 128 * LHP * 2);
        float acc[2][8][4];
#pragma unroll
        for (int m = 0; m < 2; m++)
#pragma unroll
            for (int nt = 0; nt < 8; nt++)
#pragma unroll
                for (int i = 0; i < 4; i++) acc[m][nt][i] = 0.f;

#pragma unroll
        for (int ks = 0; ks < 4; ks++) {
            uint32_t kb = ks * 32;
            uint32_t a[2][4];
            ldsm4(a[0][0], a[0][1], a[0][2], a[0][3], Ab + aoff[0] + kb);
            ldsm4(a[1][0], a[1][1], a[1][2], a[1][3], Ab + aoff[1] + kb);
#pragma unroll
            for (int p = 0; p < 4; p++) {
                uint32_t q0, q1, q2, q3;
                ldsm4(q0, q1, q2, q3, boff[p] + kb);
                mma_f16(acc[0][2 * p],     a[0][0], a[0][1], a[0][2], a[0][3], q0, q2);
                mma_f16(acc[0][2 * p + 1], a[0][0], a[0][1], a[0][2], a[0][3], q1, q3);
                mma_f16(acc[1][2 * p],     a[1][0], a[1][1], a[1][2], a[1][3], q0, q2);
                mma_f16(acc[1][2 * p + 1], a[1][0], a[1][1], a[1][2], a[1][3], q1, q3);
            }
        }

        // ---- staged epilogue ----
        __syncthreads();
        __half* S = As + buf * 128 * LHP;
        int n0 = tile * 128;
        // pass A: xs (fp16) from wq==0
        if (wq == 0) {
#pragma unroll
            for (int m = 0; m < 2; m++) {
                int lr = wm * 32 + m * 16 + g;
#pragma unroll
                for (int nt = 0; nt < 8; nt++) {
                    int col = nt * 8 + 2 * t;
                    *(__half2*)&S[lr * LHP + col] =
                        __floats2half2_rn(acc[m][nt][0], acc[m][nt][1]);
                    *(__half2*)&S[(lr + 8) * LHP + col] =
                        __floats2half2_rn(acc[m][nt][2], acc[m][nt][3]);
                }
            }
        }
        __syncthreads();
        for (int c2 = tid; c2 < 1024; c2 += 256) {
            int r = c2 >> 3, q = c2 & 7;
            int node = n0 + r;
            if (node < n)
                *(uint4*)((char*)(g_xsh + (size_t)node * 64) + q * 16) =
                    *(const uint4*)((const char*)S + r * 144 + q * 16);
        }
        __syncthreads();
        // pass B: xn (fp32) from wq==1; stage pitch 36 floats (144B)
        float* F = (float*)S;
        if (wq == 1) {
#pragma unroll
            for (int m = 0; m < 2; m++) {
                int lr = wm * 32 + m * 16 + g;
#pragma unroll
                for (int nt = 0; nt < 8; nt++) {
                    int col = nt * 8 + 2 * t;  // 0..63
                    if (col < 32) {
                        *(float2*)&F[lr * 36 + col] =
                            make_float2(acc[m][nt][0], acc[m][nt][1]);
                        *(float2*)&F[(lr + 8) * 36 + col] =
                            make_float2(acc[m][nt][2], acc[m][nt][3]);
                    }
                }
            }
        }
        __syncthreads();
        for (int c2 = tid; c2 < 1024; c2 += 256) {   // 128 rows x 8 uint4 (first 32 cols)
            int r = c2 >> 3, q = c2 & 7;
            int node = n0 + r;
            if (node < n)
                *(uint4*)((char*)(g_xnf + (size_t)node * 64) + q * 16) =
                    *(const uint4*)((const char*)F + r * 144 + q * 16);
        }
        __syncthreads();
        // pass C: xn cols 32..63
        if (wq == 1) {
#pragma unroll
            for (int m = 0; m < 2; m++) {
                int lr = wm * 32 + m * 16 + g;
#pragma unroll
                for (int nt = 0; nt < 8; nt++) {
                    int col = nt * 8 + 2 * t;
                    if (col >= 32) {
                        *(float2*)&F[lr * 36 + (col - 32)] =
                            make_float2(acc[m][nt][0], acc[m][nt][1]);
                        *(float2*)&F[(lr + 8) * 36 + (col - 32)] =
                            make_float2(acc[m][nt][2], acc[m][nt][3]);
                    }
                }
            }
        }
        __syncthreads();
        for (int c2 = tid; c2 < 1024; c2 += 256) {
            int r = c2 >> 3, q = c2 & 7;
            int node = n0 + r;
            if (node < n)
                *(uint4*)((char*)(g_xnf + (size_t)node * 64 + 32) + q * 16) =
                    *(const uint4*)((const char*)F + r * 144 + q * 16);
        }
        __syncthreads();
    }
}

// ---------------- layer-1 aggregation (half-warp per node, float4):
// h = relu(xs + b1 + invdeg * sum(xn[src]))
__global__ void k_agg1(const float* __restrict__ bias, int n) {
    int warp = (blockIdx.x * blockDim.x + threadIdx.x) >> 5;
    int lane = threadIdx.x & 31;
    int half = lane >> 4, l16 = lane & 15;
    int node = warp * 2 + half;
    if (node >= n) return;
    int start = g_rowptr[node], end = g_rowptr[node + 1];
    const float4* xn4 = (const float4*)g_xnf;
    float4 acc = make_float4(0.f, 0.f, 0.f, 0.f);
    int e = start;
    for (; e + 4 <= end; e += 4) {
        int s0 = __ldg(&g_eidx[e]),     s1 = __ldg(&g_eidx[e + 1]);
        int s2 = __ldg(&g_eidx[e + 2]), s3 = __ldg(&g_eidx[e + 3]);
        float4 a = xn4[(size_t)s0 * 16 + l16];
        float4 b = xn4[(size_t)s1 * 16 + l16];
        float4 c = xn4[(size_t)s2 * 16 + l16];
        float4 d = xn4[(size_t)s3 * 16 + l16];
        acc.x += (a.x + b.x) + (c.x + d.x);
        acc.y += (a.y + b.y) + (c.y + d.y);
        acc.z += (a.z + b.z) + (c.z + d.z);
        acc.w += (a.w + b.w) + (c.w + d.w);
    }
    for (; e < end; e++) {
        float4 a = xn4[(size_t)__ldg(&g_eidx[e]) * 16 + l16];
        acc.x += a.x; acc.y += a.y; acc.z += a.z; acc.w += a.w;
    }
    float id = g_invdeg[node];
    uint2 xsu = ((const uint2*)g_xsh)[(size_t)node * 16 + l16];
    float2 xs0 = __half22float2(*(__half2*)&xsu.x);
    float2 xs1 = __half22float2(*(__half2*)&xsu.y);
    float4 bb = __ldg((const float4*)(bias + 4 * l16));
    float h0 = fmaxf(xs0.x + bb.x + acc.x * id, 0.f);
    float h1 = fmaxf(xs0.y + bb.y + acc.y * id, 0.f);
    float h2 = fmaxf(xs1.x + bb.z + acc.z * id, 0.f);
    float h3 = fmaxf(xs1.y + bb.w + acc.w * id, 0.f);
    uint2 o;
    *(__half2*)&o.x = __floats2half2_rn(h0, h1);
    *(__half2*)&o.y = __floats2half2_rn(h2, h3);
    ((uint2*)g_hh)[(size_t)node * 16 + l16] = o;
}

// ---------------- layer-2 GEMM: [out|hn] = h @ [Ws2|Wn2], staged epilogue ----------
__global__ void __launch_bounds__(256, 2) k_hgemm2(
    const float* __restrict__ ws, const float* __restrict__ wn,
    const float* __restrict__ bias, float* __restrict__ out, int n, int ntiles)
{
    __shared__ __half Bs[64 * LHP];
    __shared__ __half As[2][128 * LHP];
    int tid = threadIdx.x, wid = tid >> 5, lane = tid & 31;

    if (blockIdx.x >= (unsigned)ntiles) return;

    for (int idx = tid; idx < 2048; idx += 256) {
        int k = idx >> 5, nn = idx & 31;
        Bs[nn * LHP + k]        = __float2half_rn(ws[idx]);
        Bs[(32 + nn) * LHP + k] = __float2half_rn(wn[idx]);
    }

    {
        int base = blockIdx.x * 128;
        for (int c = tid; c < 1024; c += 256) {
            int r = c >> 3, q = c & 7;
            int node = base + r; if (node >= n) node = n - 1;
            uint32_t sa = (uint32_t)__cvta_generic_to_shared(&As[0][r * LHP + q * 8]);
            cp16(sa, g_hh + (size_t)node * 64 + q * 8);
        }
        CP_COMMIT();
    }

    int wm = wid & 3, wq = wid >> 2;
    int g = lane >> 2, t = lane & 3;
    int rowoff = (lane & 7) + ((lane >> 3) & 1) * 8;
    int koff = (lane >> 4) * 8;

    uint32_t As_u32 = (uint32_t)__cvta_generic_to_shared(&As[0][0]);
    uint32_t Bs_u32 = (uint32_t)__cvta_generic_to_shared(&Bs[0]);
    uint32_t aoff[2], boff[2];
#pragma unroll
    for (int m = 0; m < 2; m++)
        aoff[m] = (uint32_t)(((wm * 32 + m * 16 + rowoff) * LHP + koff) * 2);
#pragma unroll
    for (int p = 0; p < 2; p++)
        boff[p] = Bs_u32 + (uint32_t)(((wq * 32 + p * 16 + rowoff) * LHP + koff) * 2);

    int buf = 0;
    for (int tile = blockIdx.x; tile < ntiles; tile += gridDim.x, buf ^= 1) {
        int nxt = tile + gridDim.x;
        if (nxt < ntiles) {
            int base = nxt * 128;
            for (int c = tid; c < 1024; c += 256) {
                int r = c >> 3, q = c & 7;
                int node = base + r; if (node >= n) node = n - 1;
                uint32_t sa = (uint32_t)__cvta_generic_to_shared(&As[buf ^ 1][r * LHP + q * 8]);
                cp16(sa, g_hh + (size_t)node * 64 + q * 8);
            }
            CP_COMMIT();
            asm volatile("cp.async.wait_group 1;" ::: "memory");
        } else {
            asm volatile("cp.async.wait_group 0;" ::: "memory");
        }
        __syncthreads();

        uint32_t Ab = As_u32 + (uint32_t)(buf * 128 * LHP * 2);
        float acc[2][4][4];
#pragma unroll
        for (int m = 0; m < 2; m++)
#pragma unroll
            for (int nt = 0; nt < 4; nt++)
#pragma unroll
                for (int i = 0; i < 4; i++) acc[m][nt][i] = 0.f;

#pragma unroll
        for (int ks = 0; ks < 4; ks++) {
            uint32_t kb = ks * 32;
            uint32_t a[2][4];
            ldsm4(a[0][0], a[0][1], a[0][2], a[0][3], Ab + aoff[0] + kb);
            ldsm4(a[1][0], a[1][1], a[1][2], a[1][3], Ab + aoff[1] + kb);
#pragma unroll
            for (int p = 0; p < 2; p++) {
                uint32_t q0, q1, q2, q3;
                ldsm4(q0, q1, q2, q3, boff[p] + kb);
                mma_f16(acc[0][2 * p],     a[0][0], a[0][1], a[0][2], a[0][3], q0, q2);
                mma_f16(acc[0][2 * p + 1], a[0][0], a[0][1], a[0][2], a[0][3], q1, q3);
                mma_f16(acc[1][2 * p],     a[1][0], a[1][1], a[1][2], a[1][3], q0, q2);
                mma_f16(acc[1][2 * p + 1], a[1][0], a[1][1], a[1][2], a[1][3], q1, q3);
            }
        }

        // ---- staged epilogue ----
        __syncthreads();
        char* Sb = (char*)&As[buf][0];
        int n0 = tile * 128;
        float* F = (float*)Sb;
        // pass A: out (fp32 + bias) from wq==0
        if (wq == 0) {
#pragma unroll
            for (int m = 0; m < 2; m++) {
                int lr = wm * 32 + m * 16 + g;
#pragma unroll
                for (int nt = 0; nt < 4; nt++) {
                    int col = nt * 8 + 2 * t;
                    float b0 = __ldg(&bias[col]);
                    float b1 = __ldg(&bias[col + 1]);
                    *(float2*)&F[lr * 36 + col] =
                        make_float2(acc[m][nt][0] + b0, acc[m][nt][1] + b1);
                    *(float2*)&F[(lr + 8) * 36 + col] =
                        make_float2(acc[m][nt][2] + b0, acc[m][nt][3] + b1);
                }
            }
        }
        __syncthreads();
        for (int c2 = tid; c2 < 1024; c2 += 256) {
            int r = c2 >> 3, q = c2 & 7;
            int node = n0 + r;
            if (node < n)
                *(uint4*)((char*)(out + (size_t)node * 32) + q * 16) =
                    *(const uint4*)(Sb + r * 144 + q * 16);
        }
        __syncthreads();
        // pass B: hn (fp32) from wq==1
        if (wq == 1) {
#pragma unroll
            for (int m = 0; m < 2; m++) {
                int lr = wm * 32 + m * 16 + g;
#pragma unroll
                for (int nt = 0; nt < 4; nt++) {
                    int col = nt * 8 + 2 * t;
                    *(float2*)&F[lr * 36 + col] =
                        make_float2(acc[m][nt][0], acc[m][nt][1]);
                    *(float2*)&F[(lr + 8) * 36 + col] =
                        make_float2(acc[m][nt][2], acc[m][nt][3]);
                }
            }
        }
        __syncthreads();
        for (int c2 = tid; c2 < 1024; c2 += 256) {
            int r = c2 >> 3, q = c2 & 7;
            int node = n0 + r;
            if (node < n)
                *(uint4*)((char*)(g_hnf + (size_t)node * 32) + q * 16) =
                    *(const uint4*)(Sb + r * 144 + q * 16);
        }
        __syncthreads();
    }
}

// ---------------- layer-2 aggregation (half-warp per node, float2):
// out += invdeg * sum(hn[src])
__global__ void k_agg2(float* __restrict__ out, int n) {
    int warp = (blockIdx.x * blockDim.x + threadIdx.x) >> 5;
    int lane = threadIdx.x & 31;
    int half = lane >> 4, l16 = lane & 15;
    int node = warp * 2 + half;
    if (node >= n) return;
    int start = g_rowptr[node], end = g_rowptr[node + 1];
    const float2* hn2 = (const float2*)g_hnf;
    float ax = 0.f, ay = 0.f;
    int e = start;
    for (; e + 4 <= end; e += 4) {
        int s0 = __ldg(&g_eidx[e]),     s1 = __ldg(&g_eidx[e + 1]);
        int s2 = __ldg(&g_eidx[e + 2]), s3 = __ldg(&g_eidx[e + 3]);
        float2 a = hn2[(size_t)s0 * 16 + l16];
        float2 b = hn2[(size_t)s1 * 16 + l16];
        float2 c = hn2[(size_t)s2 * 16 + l16];
        float2 d = hn2[(size_t)s3 * 16 + l16];
        ax += (a.x + b.x) + (c.x + d.x);
        ay += (a.y + b.y) + (c.y + d.y);
    }
    for (; e < end; e++) {
        float2 a = hn2[(size_t)__ldg(&g_eidx[e]) * 16 + l16];
        ax += a.x; ay += a.y;
    }
    float id = g_invdeg[node];
    float2* op = (float2*)(out + (size_t)node * 32) + l16;
    float2 o = *op;
    o.x += ax * id;
    o.y += ay * id;
    *op = o;
}

// ---------------- launcher (two-branch graph via event fork/join) ----------------
extern "C" void kernel_launch(void* const* d_in, const int* in_sizes, int n_in,
                              void* d_out, int out_size) {
    const float* x   = (const float*)d_in[0];
    const int*   src = (const int*)d_in[1];
    const int*   dst = (const int*)d_in[2];
    const float* ws1 = (const float*)d_in[3];
    const float* wn1 = (const float*)d_in[4];
    const float* b1  = (const float*)d_in[5];
    const float* ws2 = (const float*)d_in[6];
    const float* wn2 = (const float*)d_in[7];
    const float* b2  = (const float*)d_in[8];
    float* out = (float*)d_out;

    int N = in_sizes[0] / 64;
    int E = in_sizes[1];
    int ntiles = (N + 127) >> 7;
    int nb1 = (N + 1023) / 1024;
    int pgrid = 296;
    int aggblocks = ((N + 1) / 2 + 7) / 8;   // 2 nodes per warp, 8 warps per block

    static cudaStream_t s2 = nullptr;
    static cudaEvent_t evFork = nullptr, evJoin = nullptr;
    if (!s2) {
        cudaStreamCreateWithFlags(&s2, cudaStreamNonBlocking);
        cudaEventCreateWithFlags(&evFork, cudaEventDisableTiming);
        cudaEventCreateWithFlags(&evJoin, cudaEventDisableTiming);
        cudaFuncSetAttribute(k_hgemm1, cudaFuncAttributeMaxDynamicSharedMemorySize, HG1_SMEM);
    }

    cudaEventRecord(evFork, 0);
    cudaStreamWaitEvent(s2, evFork, 0);

    k_prep<<<(N * 32 + 255) / 256, 256>>>(x, N);                       // 1  (s0)
    k_zero_deg<<<(N + 255) / 256, 256, 0, s2>>>(N);                    // 2  (s2)
    k_count<<<(E / 4 + 255) / 256, 256, 0, s2>>>(dst, E);              // 3  (s2)
    k_hgemm1<<<pgrid, 256, HG1_SMEM>>>(ws1, wn1, N, ntiles);           // 4  (s0, profiled)
    k_scanA<<<nb1, 1024, 0, s2>>>(N);                                  // 5  (s2)
    k_scanB<<<nb1, 1024, 0, s2>>>(N, E, nb1);                          // 6  (s2)
    k_scatter<<<(E / 4 + 255) / 256, 256, 0, s2>>>(src, dst, E);       // 7  (s2)
    cudaEventRecord(evJoin, s2);

    cudaStreamWaitEvent(0, evJoin, 0);
    k_agg1<<<aggblocks, 256>>>(b1, N);                                 // 8
    k_hgemm2<<<pgrid, 256>>>(ws2, wn2, b2, out, N, ntiles);            // 9
    k_agg2<<<aggblocks, 256>>>(out, N);                                // 10
}

// round 17
// speedup vs baseline: 1.4601x; 1.4601x over previous
#include <cuda_runtime.h>
#include <cuda_fp16.h>
#include <cstdint>

#define NMAX 100000
#define EMAX 1000000

// ---------------- scratch ----------------
__device__ int    g_deg[NMAX];
__device__ int    g_rowptr[NMAX + 1];
__device__ int    g_cursor[NMAX];
__device__ float  g_invdeg[NMAX];
__device__ int    g_bsums[128];
__device__ int    g_eidx[EMAX];
__device__ __half g_xh[(size_t)NMAX * 64];   // x (fp16)
__device__ __half g_xsh[(size_t)NMAX * 64];  // x @ Ws1 (fp16)
__device__ __half g_xnh[(size_t)NMAX * 64];  // x @ Wn1 (fp16)
__device__ __half g_hh[(size_t)NMAX * 64];   // h (fp16)
__device__ __half g_hnh[(size_t)NMAX * 32];  // h @ Wn2 (fp16)

// ---------------- PTX helpers (all <= sm_80 era, no 'a' gate) ----------------
__device__ __forceinline__ void mma_f16(float c[4], uint32_t a0, uint32_t a1,
                                        uint32_t a2, uint32_t a3,
                                        uint32_t b0, uint32_t b1) {
    asm volatile(
        "mma.sync.aligned.m16n8k16.row.col.f32.f16.f16.f32 "
        "{%0,%1,%2,%3}, {%4,%5,%6,%7}, {%8,%9}, {%0,%1,%2,%3};"
        : "+f"(c[0]), "+f"(c[1]), "+f"(c[2]), "+f"(c[3])
        : "r"(a0), "r"(a1), "r"(a2), "r"(a3), "r"(b0), "r"(b1));
}
__device__ __forceinline__ void ldsm4(uint32_t& r0, uint32_t& r1, uint32_t& r2,
                                      uint32_t& r3, uint32_t addr) {
    asm volatile("ldmatrix.sync.aligned.m8n8.x4.shared.b16 {%0,%1,%2,%3}, [%4];"
        : "=r"(r0), "=r"(r1), "=r"(r2), "=r"(r3) : "r"(addr));
}
__device__ __forceinline__ void cp16(uint32_t saddr, const void* g) {
    asm volatile("cp.async.ca.shared.global [%0], [%1], 16;" :: "r"(saddr), "l"(g));
}
#define CP_COMMIT() asm volatile("cp.async.commit_group;" ::: "memory")

// ---------------- prep: x -> fp16 ----------------
__global__ void k_prep(const float* __restrict__ x, int n) {
    int i = blockIdx.x * blockDim.x + threadIdx.x;
    if (i < n * 32) {
        float2 v = ((const float2*)x)[i];
        ((__half2*)g_xh)[i] = __float22half2_rn(v);
    }
}

// ---------------- CSR build ----------------
__global__ void k_zero_deg(int n) {
    int i = blockIdx.x * blockDim.x + threadIdx.x;
    if (i < n) g_deg[i] = 0;
}

__global__ void k_count(const int* __restrict__ dst, int e) {
    int i = blockIdx.x * blockDim.x + threadIdx.x;
    int i4 = i * 4;
    if (i4 + 3 < e) {
        int4 d = *(const int4*)(dst + i4);
        atomicAdd(&g_deg[d.x], 1);
        atomicAdd(&g_deg[d.y], 1);
        atomicAdd(&g_deg[d.z], 1);
        atomicAdd(&g_deg[d.w], 1);
    } else {
        for (int j = i4; j < e; j++) atomicAdd(&g_deg[dst[j]], 1);
    }
}

__global__ void __launch_bounds__(1024) k_scanA(int n) {
    __shared__ int s[1024];
    int tid = threadIdx.x;
    int i = blockIdx.x * 1024 + tid;
    int v = (i < n) ? g_deg[i] : 0;
    s[tid] = v;
    __syncthreads();
#pragma unroll
    for (int off = 1; off < 1024; off <<= 1) {
        int t = (tid >= off) ? s[tid - off] : 0;
        __syncthreads();
        s[tid] += t;
        __syncthreads();
    }
    if (i < n) g_rowptr[i] = s[tid] - v;
    if (tid == 1023) g_bsums[blockIdx.x] = s[1023];
}

__global__ void __launch_bounds__(1024) k_scanB(int n, int e, int nb) {
    __shared__ int s[128];
    int tid = threadIdx.x;
    if (tid == 0) {
        int run = 0;
        for (int b = 0; b < nb; b++) { int v = g_bsums[b]; s[b] = run; run += v; }
    }
    __syncthreads();
    int boff = s[blockIdx.x];
    int i = blockIdx.x * 1024 + tid;
    if (i < n) {
        int rp = g_rowptr[i] + boff;
        g_rowptr[i] = rp;
        g_cursor[i] = rp;
        int d = g_deg[i];
        g_invdeg[i] = 1.0f / (float)(d > 1 ? d : 1);
    }
    if (i == 0) g_rowptr[n] = e;
}

__global__ void k_scatter(const int* __restrict__ src, const int* __restrict__ dst, int e) {
    int i = blockIdx.x * blockDim.x + threadIdx.x;
    int i4 = i * 4;
    if (i4 + 3 < e) {
        int4 d = *(const int4*)(dst + i4);
        int4 s = *(const int4*)(src + i4);
        g_eidx[atomicAdd(&g_cursor[d.x], 1)] = s.x;
        g_eidx[atomicAdd(&g_cursor[d.y], 1)] = s.y;
        g_eidx[atomicAdd(&g_cursor[d.z], 1)] = s.z;
        g_eidx[atomicAdd(&g_cursor[d.w], 1)] = s.w;
    } else {
        for (int j = i4; j < e; j++)
            g_eidx[atomicAdd(&g_cursor[dst[j]], 1)] = src[j];
    }
}

// ---------------- layer-1 GEMM: [xs|xn] = x @ [Ws1|Wn1], staged epilogue ----------
#define LHP 72
static constexpr int HG1_B = 128 * LHP * 2;                 // 18432 B
static constexpr int HG1_SMEM = HG1_B + 2 * 128 * LHP * 2;  // 55296 B

__global__ void __launch_bounds__(256, 2) k_hgemm1(
    const float* __restrict__ ws, const float* __restrict__ wn, int n, int ntiles)
{
    extern __shared__ char smraw[];
    __half* Bs = (__half*)smraw;                  // [128][LHP]
    __half* As = (__half*)(smraw + HG1_B);        // [2][128][LHP]
    int tid = threadIdx.x, wid = tid >> 5, lane = tid & 31;

    if (blockIdx.x >= (unsigned)ntiles) return;

    for (int idx = tid; idx < 4096; idx += 256) {
        int k = idx >> 6, nn = idx & 63;
        Bs[nn * LHP + k]        = __float2half_rn(ws[idx]);
        Bs[(64 + nn) * LHP + k] = __float2half_rn(wn[idx]);
    }

    {
        int base = blockIdx.x * 128;
        for (int c = tid; c < 1024; c += 256) {
            int r = c >> 3, q = c & 7;
            int node = base + r; if (node >= n) node = n - 1;
            uint32_t sa = (uint32_t)__cvta_generic_to_shared(As + r * LHP + q * 8);
            cp16(sa, g_xh + (size_t)node * 64 + q * 8);
        }
        CP_COMMIT();
    }

    int wm = wid & 3, wq = wid >> 2;
    int g = lane >> 2, t = lane & 3;
    int rowoff = (lane & 7) + ((lane >> 3) & 1) * 8;
    int koff = (lane >> 4) * 8;

    uint32_t As_u32 = (uint32_t)__cvta_generic_to_shared(As);
    uint32_t Bs_u32 = (uint32_t)__cvta_generic_to_shared(Bs);
    uint32_t aoff[2], boff[4];
#pragma unroll
    for (int m = 0; m < 2; m++)
        aoff[m] = (uint32_t)(((wm * 32 + m * 16 + rowoff) * LHP + koff) * 2);
#pragma unroll
    for (int p = 0; p < 4; p++)
        boff[p] = Bs_u32 + (uint32_t)(((wq * 64 + p * 16 + rowoff) * LHP + koff) * 2);

    int buf = 0;
    for (int tile = blockIdx.x; tile < ntiles; tile += gridDim.x, buf ^= 1) {
        int nxt = tile + gridDim.x;
        if (nxt < ntiles) {
            int base = nxt * 128;
            __half* dst = As + (buf ^ 1) * 128 * LHP;
            for (int c = tid; c < 1024; c += 256) {
                int r = c >> 3, q = c & 7;
                int node = base + r; if (node >= n) node = n - 1;
                uint32_t sa = (uint32_t)__cvta_generic_to_shared(dst + r * LHP + q * 8);
                cp16(sa, g_xh + (size_t)node * 64 + q * 8);
            }
            CP_COMMIT();
            asm volatile("cp.async.wait_group 1;" ::: "memory");
        } else {
            asm volatile("cp.async.wait_group 0;" ::: "memory");
        }
        __syncthreads();

        uint32_t Ab = As_u32 + (uint32_t)(buf * 128 * LHP * 2);
        float acc[2][8][4];
#pragma unroll
        for (int m = 0; m < 2; m++)
#pragma unroll
            for (int nt = 0; nt < 8; nt++)
#pragma unroll
                for (int i = 0; i < 4; i++) acc[m][nt][i] = 0.f;

#pragma unroll
        for (int ks = 0; ks < 4; ks++) {
            uint32_t kb = ks * 32;
            uint32_t a[2][4];
            ldsm4(a[0][0], a[0][1], a[0][2], a[0][3], Ab + aoff[0] + kb);
            ldsm4(a[1][0], a[1][1], a[1][2], a[1][3], Ab + aoff[1] + kb);
#pragma unroll
            for (int p = 0; p < 4; p++) {
                uint32_t q0, q1, q2, q3;
                ldsm4(q0, q1, q2, q3, boff[p] + kb);
                mma_f16(acc[0][2 * p],     a[0][0], a[0][1], a[0][2], a[0][3], q0, q2);
                mma_f16(acc[0][2 * p + 1], a[0][0], a[0][1], a[0][2], a[0][3], q1, q3);
                mma_f16(acc[1][2 * p],     a[1][0], a[1][1], a[1][2], a[1][3], q0, q2);
                mma_f16(acc[1][2 * p + 1], a[1][0], a[1][1], a[1][2], a[1][3], q1, q3);
            }
        }

        // ---- staged epilogue ----
        __syncthreads();
        __half* S = As + buf * 128 * LHP;
        int n0 = tile * 128;
        if (wq == 0) {
#pragma unroll
            for (int m = 0; m < 2; m++) {
                int lr = wm * 32 + m * 16 + g;
#pragma unroll
                for (int nt = 0; nt < 8; nt++) {
                    int col = nt * 8 + 2 * t;
                    *(__half2*)&S[lr * LHP + col] =
                        __floats2half2_rn(acc[m][nt][0], acc[m][nt][1]);
                    *(__half2*)&S[(lr + 8) * LHP + col] =
                        __floats2half2_rn(acc[m][nt][2], acc[m][nt][3]);
                }
            }
        }
        __syncthreads();
        for (int c2 = tid; c2 < 1024; c2 += 256) {
            int r = c2 >> 3, q = c2 & 7;
            int node = n0 + r;
            if (node < n)
                *(uint4*)((char*)(g_xsh + (size_t)node * 64) + q * 16) =
                    *(const uint4*)((const char*)S + r * 144 + q * 16);
        }
        __syncthreads();
        if (wq == 1) {
#pragma unroll
            for (int m = 0; m < 2; m++) {
                int lr = wm * 32 + m * 16 + g;
#pragma unroll
                for (int nt = 0; nt < 8; nt++) {
                    int col = nt * 8 + 2 * t;
                    *(__half2*)&S[lr * LHP + col] =
                        __floats2half2_rn(acc[m][nt][0], acc[m][nt][1]);
                    *(__half2*)&S[(lr + 8) * LHP + col] =
                        __floats2half2_rn(acc[m][nt][2], acc[m][nt][3]);
                }
            }
        }
        __syncthreads();
        for (int c2 = tid; c2 < 1024; c2 += 256) {
            int r = c2 >> 3, q = c2 & 7;
            int node = n0 + r;
            if (node < n)
                *(uint4*)((char*)(g_xnh + (size_t)node * 64) + q * 16) =
                    *(const uint4*)((const char*)S + r * 144 + q * 16);
        }
        __syncthreads();
    }
}

// ---------------- layer-1 aggregation (half-warp per node, fp16 HADD2):
// h = relu(xs + b1 + invdeg * sum(xn[src]))
__global__ void k_agg1(const float* __restrict__ bias, int n) {
    int warp = (blockIdx.x * blockDim.x + threadIdx.x) >> 5;
    int lane = threadIdx.x & 31;
    int half = lane >> 4, l16 = lane & 15;
    int node = warp * 2 + half;
    if (node >= n) return;
    int start = g_rowptr[node], end = g_rowptr[node + 1];
    const uint2* xn2 = (const uint2*)g_xnh;   // row = 16 uint2 (64 halves)

    __half2 z = __float2half2_rn(0.f);
    __half2 acc[2][2] = {{z, z}, {z, z}};     // [edge parity][x/y]
    int e = start;
    for (; e + 2 <= end; e += 2) {
        int s0 = __ldg(&g_eidx[e]), s1 = __ldg(&g_eidx[e + 1]);
        uint2 v0 = xn2[(size_t)s0 * 16 + l16];
        uint2 v1 = xn2[(size_t)s1 * 16 + l16];
        acc[0][0] = __hadd2(acc[0][0], *(__half2*)&v0.x);
        acc[0][1] = __hadd2(acc[0][1], *(__half2*)&v0.y);
        acc[1][0] = __hadd2(acc[1][0], *(__half2*)&v1.x);
        acc[1][1] = __hadd2(acc[1][1], *(__half2*)&v1.y);
    }
    if (e < end) {
        int s0 = __ldg(&g_eidx[e]);
        uint2 v0 = xn2[(size_t)s0 * 16 + l16];
        acc[0][0] = __hadd2(acc[0][0], *(__half2*)&v0.x);
        acc[0][1] = __hadd2(acc[0][1], *(__half2*)&v0.y);
    }
    float2 a0 = __half22float2(acc[0][0]);
    float2 a1 = __half22float2(acc[1][0]);
    float2 b0 = __half22float2(acc[0][1]);
    float2 b1 = __half22float2(acc[1][1]);
    float sx0 = a0.x + a1.x, sx1 = a0.y + a1.y;
    float sx2 = b0.x + b1.x, sx3 = b0.y + b1.y;

    float id = g_invdeg[node];
    uint2 xsu = ((const uint2*)g_xsh)[(size_t)node * 16 + l16];
    float2 xs0 = __half22float2(*(__half2*)&xsu.x);
    float2 xs1 = __half22float2(*(__half2*)&xsu.y);
    float4 bb = __ldg((const float4*)(bias + 4 * l16));
    float h0 = fmaxf(xs0.x + bb.x + sx0 * id, 0.f);
    float h1 = fmaxf(xs0.y + bb.y + sx1 * id, 0.f);
    float h2 = fmaxf(xs1.x + bb.z + sx2 * id, 0.f);
    float h3 = fmaxf(xs1.y + bb.w + sx3 * id, 0.f);
    uint2 o;
    *(__half2*)&o.x = __floats2half2_rn(h0, h1);
    *(__half2*)&o.y = __floats2half2_rn(h2, h3);
    ((uint2*)g_hh)[(size_t)node * 16 + l16] = o;
}

// ---------------- layer-2 GEMM: [out|hn] = h @ [Ws2|Wn2], staged epilogue ----------
__global__ void __launch_bounds__(256, 2) k_hgemm2(
    const float* __restrict__ ws, const float* __restrict__ wn,
    const float* __restrict__ bias, float* __restrict__ out, int n, int ntiles)
{
    __shared__ __half Bs[64 * LHP];
    __shared__ __half As[2][128 * LHP];
    int tid = threadIdx.x, wid = tid >> 5, lane = tid & 31;

    if (blockIdx.x >= (unsigned)ntiles) return;

    for (int idx = tid; idx < 2048; idx += 256) {
        int k = idx >> 5, nn = idx & 31;
        Bs[nn * LHP + k]        = __float2half_rn(ws[idx]);
        Bs[(32 + nn) * LHP + k] = __float2half_rn(wn[idx]);
    }

    {
        int base = blockIdx.x * 128;
        for (int c = tid; c < 1024; c += 256) {
            int r = c >> 3, q = c & 7;
            int node = base + r; if (node >= n) node = n - 1;
            uint32_t sa = (uint32_t)__cvta_generic_to_shared(&As[0][r * LHP + q * 8]);
            cp16(sa, g_hh + (size_t)node * 64 + q * 8);
        }
        CP_COMMIT();
    }

    int wm = wid & 3, wq = wid >> 2;
    int g = lane >> 2, t = lane & 3;
    int rowoff = (lane & 7) + ((lane >> 3) & 1) * 8;
    int koff = (lane >> 4) * 8;

    uint32_t As_u32 = (uint32_t)__cvta_generic_to_shared(&As[0][0]);
    uint32_t Bs_u32 = (uint32_t)__cvta_generic_to_shared(&Bs[0]);
    uint32_t aoff[2], boff[2];
#pragma unroll
    for (int m = 0; m < 2; m++)
        aoff[m] = (uint32_t)(((wm * 32 + m * 16 + rowoff) * LHP + koff) * 2);
#pragma unroll
    for (int p = 0; p < 2; p++)
        boff[p] = Bs_u32 + (uint32_t)(((wq * 32 + p * 16 + rowoff) * LHP + koff) * 2);

    int buf = 0;
    for (int tile = blockIdx.x; tile < ntiles; tile += gridDim.x, buf ^= 1) {
        int nxt = tile + gridDim.x;
        if (nxt < ntiles) {
            int base = nxt * 128;
            for (int c = tid; c < 1024; c += 256) {
                int r = c >> 3, q = c & 7;
                int node = base + r; if (node >= n) node = n - 1;
                uint32_t sa = (uint32_t)__cvta_generic_to_shared(&As[buf ^ 1][r * LHP + q * 8]);
                cp16(sa, g_hh + (size_t)node * 64 + q * 8);
            }
            CP_COMMIT();
            asm volatile("cp.async.wait_group 1;" ::: "memory");
        } else {
            asm volatile("cp.async.wait_group 0;" ::: "memory");
        }
        __syncthreads();

        uint32_t Ab = As_u32 + (uint32_t)(buf * 128 * LHP * 2);
        float acc[2][4][4];
#pragma unroll
        for (int m = 0; m < 2; m++)
#pragma unroll
            for (int nt = 0; nt < 4; nt++)
#pragma unroll
                for (int i = 0; i < 4; i++) acc[m][nt][i] = 0.f;

#pragma unroll
        for (int ks = 0; ks < 4; ks++) {
            uint32_t kb = ks * 32;
            uint32_t a[2][4];
            ldsm4(a[0][0], a[0][1], a[0][2], a[0][3], Ab + aoff[0] + kb);
            ldsm4(a[1][0], a[1][1], a[1][2], a[1][3], Ab + aoff[1] + kb);
#pragma unroll
            for (int p = 0; p < 2; p++) {
                uint32_t q0, q1, q2, q3;
                ldsm4(q0, q1, q2, q3, boff[p] + kb);
                mma_f16(acc[0][2 * p],     a[0][0], a[0][1], a[0][2], a[0][3], q0, q2);
                mma_f16(acc[0][2 * p + 1], a[0][0], a[0][1], a[0][2], a[0][3], q1, q3);
                mma_f16(acc[1][2 * p],     a[1][0], a[1][1], a[1][2], a[1][3], q0, q2);
                mma_f16(acc[1][2 * p + 1], a[1][0], a[1][1], a[1][2], a[1][3], q1, q3);
            }
        }

        // ---- staged epilogue ----
        __syncthreads();
        char* Sb = (char*)&As[buf][0];
        int n0 = tile * 128;
        float* F = (float*)Sb;
        if (wq == 0) {
#pragma unroll
            for (int m = 0; m < 2; m++) {
                int lr = wm * 32 + m * 16 + g;
#pragma unroll
                for (int nt = 0; nt < 4; nt++) {
                    int col = nt * 8 + 2 * t;
                    float b0 = __ldg(&bias[col]);
                    float b1 = __ldg(&bias[col + 1]);
                    *(float2*)&F[lr * 36 + col] =
                        make_float2(acc[m][nt][0] + b0, acc[m][nt][1] + b1);
                    *(float2*)&F[(lr + 8) * 36 + col] =
                        make_float2(acc[m][nt][2] + b0, acc[m][nt][3] + b1);
                }
            }
        }
        __syncthreads();
        for (int c2 = tid; c2 < 1024; c2 += 256) {
            int r = c2 >> 3, q = c2 & 7;
            int node = n0 + r;
            if (node < n)
                *(uint4*)((char*)(out + (size_t)node * 32) + q * 16) =
                    *(const uint4*)(Sb + r * 144 + q * 16);
        }
        __syncthreads();
        __half* H = (__half*)Sb;
        if (wq == 1) {
#pragma unroll
            for (int m = 0; m < 2; m++) {
                int lr = wm * 32 + m * 16 + g;
#pragma unroll
                for (int nt = 0; nt < 4; nt++) {
                    int col = nt * 8 + 2 * t;
                    *(__half2*)&H[lr * LHP + col] =
                        __floats2half2_rn(acc[m][nt][0], acc[m][nt][1]);
                    *(__half2*)&H[(lr + 8) * LHP + col] =
                        __floats2half2_rn(acc[m][nt][2], acc[m][nt][3]);
                }
            }
        }
        __syncthreads();
        for (int c2 = tid; c2 < 512; c2 += 256) {
            int r = c2 >> 2, q = c2 & 3;
            int node = n0 + r;
            if (node < n)
                *(uint4*)((char*)(g_hnh + (size_t)node * 32) + q * 16) =
                    *(const uint4*)(Sb + r * 144 + q * 16);
        }
        __syncthreads();
    }
}

// ---------------- layer-2 aggregation (half-warp per node, fp16 HADD2):
// out += invdeg * sum(hn[src])
__global__ void k_agg2(float* __restrict__ out, int n) {
    int warp = (blockIdx.x * blockDim.x + threadIdx.x) >> 5;
    int lane = threadIdx.x & 31;
    int half = lane >> 4, l16 = lane & 15;
    int node = warp * 2 + half;
    if (node >= n) return;
    int start = g_rowptr[node], end = g_rowptr[node + 1];
    const uint32_t* hn2 = (const uint32_t*)g_hnh;   // row = 16 half2 (32 halves)

    __half2 z = __float2half2_rn(0.f);
    __half2 acc0 = z, acc1 = z;
    int e = start;
    for (; e + 2 <= end; e += 2) {
        int s0 = __ldg(&g_eidx[e]), s1 = __ldg(&g_eidx[e + 1]);
        uint32_t v0 = hn2[(size_t)s0 * 16 + l16];
        uint32_t v1 = hn2[(size_t)s1 * 16 + l16];
        acc0 = __hadd2(acc0, *(__half2*)&v0);
        acc1 = __hadd2(acc1, *(__half2*)&v1);
    }
    if (e < end) {
        uint32_t v0 = hn2[(size_t)__ldg(&g_eidx[e]) * 16 + l16];
        acc0 = __hadd2(acc0, *(__half2*)&v0);
    }
    float2 a0 = __half22float2(acc0);
    float2 a1 = __half22float2(acc1);
    float id = g_invdeg[node];
    float2* op = (float2*)(out + (size_t)node * 32) + l16;
    float2 o = *op;
    o.x += (a0.x + a1.x) * id;
    o.y += (a0.y + a1.y) * id;
    *op = o;
}

// ---------------- launcher (two-branch graph via event fork/join) ----------------
extern "C" void kernel_launch(void* const* d_in, const int* in_sizes, int n_in,
                              void* d_out, int out_size) {
    const float* x   = (const float*)d_in[0];
    const int*   src = (const int*)d_in[1];
    const int*   dst = (const int*)d_in[2];
    const float* ws1 = (const float*)d_in[3];
    const float* wn1 = (const float*)d_in[4];
    const float* b1  = (const float*)d_in[5];
    const float* ws2 = (const float*)d_in[6];
    const float* wn2 = (const float*)d_in[7];
    const float* b2  = (const float*)d_in[8];
    float* out = (float*)d_out;

    int N = in_sizes[0] / 64;
    int E = in_sizes[1];
    int ntiles = (N + 127) >> 7;
    int nb1 = (N + 1023) / 1024;
    int pgrid = 296;
    int aggblocks = ((N + 1) / 2 + 7) / 8;   // 2 nodes per warp, 8 warps per block

    static cudaStream_t s2 = nullptr;
    static cudaEvent_t evFork = nullptr, evJoin = nullptr;
    if (!s2) {
        cudaStreamCreateWithFlags(&s2, cudaStreamNonBlocking);
        cudaEventCreateWithFlags(&evFork, cudaEventDisableTiming);
        cudaEventCreateWithFlags(&evJoin, cudaEventDisableTiming);
        cudaFuncSetAttribute(k_hgemm1, cudaFuncAttributeMaxDynamicSharedMemorySize, HG1_SMEM);
    }

    cudaEventRecord(evFork, 0);
    cudaStreamWaitEvent(s2, evFork, 0);

    k_prep<<<(N * 32 + 255) / 256, 256>>>(x, N);                       // 1  (s0)
    k_zero_deg<<<(N + 255) / 256, 256, 0, s2>>>(N);                    // 2  (s2)
    k_count<<<(E / 4 + 255) / 256, 256, 0, s2>>>(dst, E);              // 3  (s2)
    k_hgemm1<<<pgrid, 256, HG1_SMEM>>>(ws1, wn1, N, ntiles);           // 4  (s0, profiled)
    k_scanA<<<nb1, 1024, 0, s2>>>(N);                                  // 5  (s2)
    k_scanB<<<nb1, 1024, 0, s2>>>(N, E, nb1);                          // 6  (s2)
    k_scatter<<<(E / 4 + 255) / 256, 256, 0, s2>>>(src, dst, E);       // 7  (s2)
    cudaEventRecord(evJoin, s2);

    cudaStreamWaitEvent(0, evJoin, 0);
    k_agg1<<<aggblocks, 256>>>(b1, N);                                 // 8
    k_hgemm2<<<pgrid, 256>>>(ws2, wn2, b2, out, N, ntiles);            // 9
    k_agg2<<<aggblocks, 256>>>(out, N);                                // 10
}